// round 2
// baseline (speedup 1.0000x reference)
#include <cuda_runtime.h>
#include <math.h>

#define B_    1024
#define HID   256
#define HGEN  512
#define VOC   5
#define EMBD  64
#define LMAX  100
#define NB    256     // persistent grid: 256 blocks, 2/SM guaranteed resident
#define NTHR  256

// ---------------- static device scratch ----------------
__device__ float g_y0[(size_t)2 * LMAX * B_ * 2 * HID];   // [seq][t][b][512] layer-0 outputs
__device__ float g_z [(size_t)4 * B_ * 4 * HGEN / 2];     // gate scratch (max 4*B*1024 enc, B*2048 dec)
__device__ float g_c0[(size_t)4 * B_ * HID];
__device__ float g_h1[(size_t)4 * B_ * HID];
__device__ float g_c1[(size_t)4 * B_ * HID];
__device__ float g_tab0 [2 * VOC * 4 * HID];              // emb @ ctx0_Wih^T per dir
__device__ float g_tabg0[VOC * 4 * HGEN];                 // emb @ gen0_Wih^T
__device__ float g_h0d[(size_t)B_ * HGEN];
__device__ float g_c0d[(size_t)B_ * HGEN];
__device__ float g_h1d[(size_t)B_ * HGEN];
__device__ float g_c1d[(size_t)B_ * HGEN];
__device__ int   g_tok[B_];

// ---------------- software grid barrier (all NB blocks resident) ----------------
__device__ unsigned g_cnt;
__device__ volatile unsigned g_gen;

__device__ __forceinline__ void gbar() {
    __syncthreads();
    __threadfence();                       // release this block's writes
    if (threadIdx.x == 0) {
        unsigned gen = g_gen;
        if (atomicAdd(&g_cnt, 1u) == NB - 1u) {
            g_cnt = 0;
            __threadfence();
            g_gen = gen + 1u;
        } else {
            while (g_gen == gen) { }
        }
        __threadfence();                   // acquire
    }
    __syncthreads();
}

// ---------------- GEMM tile: Z[128x64] += A0@W0^T (+A1@W1^T), NT, K-contig ----------------
#define BM 128
#define BN 64
#define BKK 16

__device__ __forceinline__ void gemm_pair(
    const float* __restrict__ A, int lda,
    const float* __restrict__ W, int K,
    int rowBase, int colBase,
    float (&acc)[8][4],
    float (*sA)[BM], float (*sB)[BN],
    int tid, int tx, int ty)
{
    for (int k0 = 0; k0 < K; k0 += BKK) {
        #pragma unroll
        for (int r = 0; r < 2; r++) {
            int idx = tid * 2 + r;
            int row = idx >> 2;
            int kv  = (idx & 3) * 4;
            float4 v = *reinterpret_cast<const float4*>(A + (size_t)(rowBase + row) * lda + k0 + kv);
            sA[kv + 0][row] = v.x; sA[kv + 1][row] = v.y;
            sA[kv + 2][row] = v.z; sA[kv + 3][row] = v.w;
        }
        {
            int row = tid >> 2;
            int kv  = (tid & 3) * 4;
            float4 v = *reinterpret_cast<const float4*>(W + (size_t)(colBase + row) * K + k0 + kv);
            sB[kv + 0][row] = v.x; sB[kv + 1][row] = v.y;
            sB[kv + 2][row] = v.z; sB[kv + 3][row] = v.w;
        }
        __syncthreads();
        #pragma unroll
        for (int k = 0; k < BKK; k++) {
            float a[8], bb[4];
            *reinterpret_cast<float4*>(&a[0]) = *reinterpret_cast<const float4*>(&sA[k][ty * 8]);
            *reinterpret_cast<float4*>(&a[4]) = *reinterpret_cast<const float4*>(&sA[k][ty * 8 + 4]);
            *reinterpret_cast<float4*>(&bb[0]) = *reinterpret_cast<const float4*>(&sB[k][tx * 4]);
            #pragma unroll
            for (int i = 0; i < 8; i++)
                #pragma unroll
                for (int j = 0; j < 4; j++)
                    acc[i][j] += a[i] * bb[j];
        }
        __syncthreads();
    }
}

__device__ __forceinline__ void gemm_tile(
    const float* A0, int lda0, const float* W0, int K0,
    const float* A1, int lda1, const float* W1, int K1,
    float* Z, int N, int rowBase, int colBase,
    float (*sA)[BM], float (*sB)[BN])
{
    const int tid = threadIdx.x;
    const int tx = tid & 15, ty = tid >> 4;
    float acc[8][4];
    #pragma unroll
    for (int i = 0; i < 8; i++)
        #pragma unroll
        for (int j = 0; j < 4; j++) acc[i][j] = 0.f;

    gemm_pair(A0, lda0, W0, K0, rowBase, colBase, acc, sA, sB, tid, tx, ty);
    if (K1 > 0)
        gemm_pair(A1, lda1, W1, K1, rowBase, colBase, acc, sA, sB, tid, tx, ty);

    #pragma unroll
    for (int i = 0; i < 8; i++) {
        float4 v = make_float4(acc[i][0], acc[i][1], acc[i][2], acc[i][3]);
        *reinterpret_cast<float4*>(Z + (size_t)(rowBase + ty * 8 + i) * N + colBase + tx * 4) = v;
    }
}

__device__ __forceinline__ float sigf(float x) { return 1.f / (1.f + expf(-x)); }

// ---------------- setup: tables + zero state ----------------
__global__ void setup_kernel(const float* __restrict__ emb,
                             const float* __restrict__ c0Wih,
                             const float* __restrict__ g0Wih) {
    int idx = blockIdx.x * blockDim.x + threadIdx.x;
    int stride = gridDim.x * blockDim.x;
    for (int i = idx; i < 4 * B_ * HID; i += stride) { g_c0[i] = 0.f; g_c1[i] = 0.f; }
    for (int i = idx; i < B_ * HGEN; i += stride)    { g_c0d[i] = 0.f; g_c1d[i] = 0.f; }
    for (int i = idx; i < B_; i += stride)           g_tok[i] = 0;

    for (int i = idx; i < 2 * VOC * 4 * HID; i += stride) {
        int n = i % (4 * HID);
        int v = (i / (4 * HID)) % VOC;
        int d = i / (4 * HID * VOC);
        const float* e = emb + v * EMBD;
        const float* w = c0Wih + ((size_t)d * 4 * HID + n) * EMBD;
        float s = 0.f;
        #pragma unroll
        for (int k = 0; k < EMBD; k++) s += e[k] * w[k];
        g_tab0[i] = s;
    }
    for (int i = idx; i < VOC * 4 * HGEN; i += stride) {
        int n = i % (4 * HGEN);
        int v = i / (4 * HGEN);
        const float* e = emb + v * EMBD;
        const float* w = g0Wih + (size_t)n * EMBD;
        float s = 0.f;
        #pragma unroll
        for (int k = 0; k < EMBD; k++) s += e[k] * w[k];
        g_tabg0[i] = s;
    }
}

// ---------------- encoder: persistent, whole bidirectional stack ----------------
__global__ __launch_bounds__(NTHR, 2) void encoder_kernel(
    const int* __restrict__ leftC, const int* __restrict__ rightC,
    const float* __restrict__ c0Whh, const float* __restrict__ c0b,
    const float* __restrict__ c1Wih, const float* __restrict__ c1Whh,
    const float* __restrict__ c1b, int L)
{
    __shared__ float sA[BKK][BM];
    __shared__ float sB[BKK][BN];
    const int bid = blockIdx.x, tid = threadIdx.x;

    // -------- layer 0: 4 units (seq x dir), L steps --------
    for (int t = 0; t < L; t++) {
        if (t > 0) {
            for (int tile = bid; tile < 512; tile += NB) {
                int u = tile >> 7, rem = tile & 127;
                int mt = rem >> 4, nt = rem & 15;
                int seq = u >> 1, dir = u & 1;
                int time  = dir ? (L - 1 - t) : t;
                int ptime = dir ? (time + 1) : (time - 1);
                const float* A0 = g_y0 + ((size_t)(seq * LMAX + ptime) * B_) * (2 * HID) + dir * HID;
                const float* W0 = c0Whh + (size_t)dir * 4 * HID * HID;
                gemm_tile(A0, 2 * HID, W0, HID, nullptr, 0, nullptr, 0,
                          g_z + (size_t)u * B_ * 4 * HID, 4 * HID, mt * BM, nt * BN, sA, sB);
            }
            gbar();
        }
        for (int idx = bid * NTHR + tid; idx < 4 * B_ * HID; idx += NB * NTHR) {
            int u = idx / (B_ * HID), rem = idx % (B_ * HID);
            int b = rem / HID, j = rem % HID;
            int seq = u >> 1, dir = u & 1;
            int time = dir ? (L - 1 - t) : t;
            const int* ctx = seq ? rightC : leftC;
            int v = ctx[b * L + time];
            const float* tr = g_tab0 + ((size_t)dir * VOC + v) * (4 * HID);
            const float* bb = c0b + (size_t)dir * 4 * HID;
            float zi = tr[j] + bb[j];
            float zf = tr[HID + j] + bb[HID + j];
            float zg = tr[2 * HID + j] + bb[2 * HID + j];
            float zo = tr[3 * HID + j] + bb[3 * HID + j];
            float cprev = 0.f;
            if (t > 0) {
                const float* zr = g_z + ((size_t)u * B_ + b) * 4 * HID;
                zi += zr[j]; zf += zr[HID + j]; zg += zr[2 * HID + j]; zo += zr[3 * HID + j];
                cprev = g_c0[(size_t)u * B_ * HID + rem];
            }
            float c = sigf(zf) * cprev + sigf(zi) * tanhf(zg);
            g_c0[(size_t)u * B_ * HID + rem] = c;
            g_y0[((size_t)(seq * LMAX + time) * B_ + b) * (2 * HID) + dir * HID + j] = sigf(zo) * tanhf(c);
        }
        gbar();
    }

    // -------- layer 1: u0=left-fwd(full), u1=right-bwd(full), u2=left-bwd(1), u3=right-fwd(1) --------
    for (int s = 0; s < L; s++) {
        int nu = s ? 2 : 4;
        for (int tile = bid; tile < nu * 128; tile += NB) {
            int u = tile >> 7, rem = tile & 127;
            int mt = rem >> 4, nt = rem & 15;
            int seq = (u == 0 || u == 2) ? 0 : 1;
            int dir = (u == 1 || u == 2) ? 1 : 0;
            int time = dir ? (L - 1 - s) : s;
            const float* A0 = g_y0 + ((size_t)(seq * LMAX + time) * B_) * (2 * HID);
            const float* W0 = c1Wih + (size_t)dir * 4 * HID * 2 * HID;
            const float* A1 = nullptr; const float* W1 = nullptr; int K1 = 0;
            if (s) { A1 = g_h1 + (size_t)u * B_ * HID; W1 = c1Whh + (size_t)dir * 4 * HID * HID; K1 = HID; }
            gemm_tile(A0, 2 * HID, W0, 2 * HID, A1, HID, W1, K1,
                      g_z + (size_t)u * B_ * 4 * HID, 4 * HID, mt * BM, nt * BN, sA, sB);
        }
        gbar();
        for (int idx = bid * NTHR + tid; idx < nu * B_ * HID; idx += NB * NTHR) {
            int u = idx / (B_ * HID), rem = idx % (B_ * HID);
            int b = rem / HID, j = rem % HID;
            int dir = (u == 1 || u == 2) ? 1 : 0;
            const float* zr = g_z + ((size_t)u * B_ + b) * 4 * HID;
            const float* bb = c1b + (size_t)dir * 4 * HID;
            float zi = zr[j] + bb[j];
            float zf = zr[HID + j] + bb[HID + j];
            float zg = zr[2 * HID + j] + bb[2 * HID + j];
            float zo = zr[3 * HID + j] + bb[3 * HID + j];
            float cprev = s ? g_c1[(size_t)u * B_ * HID + rem] : 0.f;
            float c = sigf(zf) * cprev + sigf(zi) * tanhf(zg);
            g_c1[(size_t)u * B_ * HID + rem] = c;
            g_h1[(size_t)u * B_ * HID + rem] = sigf(zo) * tanhf(c);
        }
        gbar();
    }

    // -------- combine = 0.5*(left_final + right_final) -> decoder h0/h1 --------
    for (int idx = bid * NTHR + tid; idx < B_ * HGEN; idx += NB * NTHR) {
        int b = idx / HGEN, j = idx % HGEN;
        float lf, rf;
        if (j < HID) {
            lf = g_h1[((size_t)0 * B_ + b) * HID + j];
            rf = g_h1[((size_t)3 * B_ + b) * HID + j];
        } else {
            int jj = j - HID;
            lf = g_h1[((size_t)2 * B_ + b) * HID + jj];
            rf = g_h1[((size_t)1 * B_ + b) * HID + jj];
        }
        float v = 0.5f * (lf + rf);
        g_h0d[idx] = v;
        g_h1d[idx] = v;
    }
}

// ---------------- decoder: persistent, T greedy steps ----------------
__global__ __launch_bounds__(NTHR, 2) void decoder_kernel(
    const float* __restrict__ g0Whh, const float* __restrict__ g0b,
    const float* __restrict__ g1Wih, const float* __restrict__ g1Whh,
    const float* __restrict__ g1b,
    const float* __restrict__ outW, const float* __restrict__ outb,
    float* __restrict__ out, int T)
{
    __shared__ float sA[BKK][BM];
    __shared__ float sB[BKK][BN];
    __shared__ float sH[4][HGEN];
    const int bid = blockIdx.x, tid = threadIdx.x;

    for (int t = 0; t < T; t++) {
        // gen0: z = h0 @ g0Whh^T (token part added via table in pw0). 256 tiles, 1/block.
        {
            int mt = bid >> 5, nt = bid & 31;
            gemm_tile(g_h0d, HGEN, g0Whh, HGEN, nullptr, 0, nullptr, 0,
                      g_z, 4 * HGEN, mt * BM, nt * BN, sA, sB);
        }
        gbar();
        // pw0
        for (int idx = bid * NTHR + tid; idx < B_ * HGEN; idx += NB * NTHR) {
            int b = idx >> 9, j = idx & (HGEN - 1);
            const float* zr = g_z + (size_t)b * 4 * HGEN;
            const float* tr = g_tabg0 + (size_t)g_tok[b] * 4 * HGEN;
            float zi = zr[j] + tr[j] + g0b[j];
            float zf = zr[HGEN + j] + tr[HGEN + j] + g0b[HGEN + j];
            float zg = zr[2 * HGEN + j] + tr[2 * HGEN + j] + g0b[2 * HGEN + j];
            float zo = zr[3 * HGEN + j] + tr[3 * HGEN + j] + g0b[3 * HGEN + j];
            float c = sigf(zf) * g_c0d[idx] + sigf(zi) * tanhf(zg);
            g_c0d[idx] = c;
            g_h0d[idx] = sigf(zo) * tanhf(c);
        }
        gbar();
        // gen1: z = h0 @ g1Wih^T + h1 @ g1Whh^T
        {
            int mt = bid >> 5, nt = bid & 31;
            gemm_tile(g_h0d, HGEN, g1Wih, HGEN, g_h1d, HGEN, g1Whh, HGEN,
                      g_z, 4 * HGEN, mt * BM, nt * BN, sA, sB);
        }
        gbar();
        // pw1 + logits fused: block owns rows bid*4 .. bid*4+3
        for (int r = 0; r < 4; r++) {
            int row = bid * 4 + r;
            const float* zr = g_z + (size_t)row * 4 * HGEN;
            for (int j = tid; j < HGEN; j += NTHR) {
                float zi = zr[j] + g1b[j];
                float zf = zr[HGEN + j] + g1b[HGEN + j];
                float zg = zr[2 * HGEN + j] + g1b[2 * HGEN + j];
                float zo = zr[3 * HGEN + j] + g1b[3 * HGEN + j];
                size_t ix = (size_t)row * HGEN + j;
                float c = sigf(zf) * g_c1d[ix] + sigf(zi) * tanhf(zg);
                g_c1d[ix] = c;
                float h = sigf(zo) * tanhf(c);
                g_h1d[ix] = h;
                sH[r][j] = h;
            }
        }
        __syncthreads();
        {
            int w = tid >> 5, lane = tid & 31;
            if (w < 4) {
                int row = bid * 4 + w;
                float a0 = 0.f, a1 = 0.f, a2 = 0.f, a3 = 0.f, a4 = 0.f;
                for (int k = lane; k < HGEN; k += 32) {
                    float hv = sH[w][k];
                    a0 += hv * outW[0 * HGEN + k];
                    a1 += hv * outW[1 * HGEN + k];
                    a2 += hv * outW[2 * HGEN + k];
                    a3 += hv * outW[3 * HGEN + k];
                    a4 += hv * outW[4 * HGEN + k];
                }
                #pragma unroll
                for (int off = 16; off; off >>= 1) {
                    a0 += __shfl_down_sync(0xffffffffu, a0, off);
                    a1 += __shfl_down_sync(0xffffffffu, a1, off);
                    a2 += __shfl_down_sync(0xffffffffu, a2, off);
                    a3 += __shfl_down_sync(0xffffffffu, a3, off);
                    a4 += __shfl_down_sync(0xffffffffu, a4, off);
                }
                if (lane == 0) {
                    float L0 = a0 + outb[0], L1 = a1 + outb[1], L2 = a2 + outb[2],
                          L3 = a3 + outb[3], L4 = a4 + outb[4];
                    float* op = out + ((size_t)row * T + t) * VOC;
                    op[0] = L0; op[1] = L1; op[2] = L2; op[3] = L3; op[4] = L4;
                    int bi = 0; float best = L0;                 // first-max = jnp.argmax
                    if (L1 > best) { best = L1; bi = 1; }
                    if (L2 > best) { best = L2; bi = 2; }
                    if (L3 > best) { best = L3; bi = 3; }
                    if (L4 > best) { best = L4; bi = 4; }
                    g_tok[row] = bi;
                }
            }
        }
        gbar();
    }
}

// ---------------- orchestration: 3 kernel nodes total ----------------
extern "C" void kernel_launch(void* const* d_in, const int* in_sizes, int n_in,
                              void* d_out, int out_size) {
    int ei = (in_sizes[2] == 1) ? 3 : 2;
    const int*   leftC  = (const int*)d_in[0];
    const int*   rightC = (const int*)d_in[1];
    const float* emb    = (const float*)d_in[ei + 0];
    const float* c0Wih  = (const float*)d_in[ei + 1];
    const float* c0Whh  = (const float*)d_in[ei + 2];
    const float* c0b    = (const float*)d_in[ei + 3];
    const float* c1Wih  = (const float*)d_in[ei + 4];
    const float* c1Whh  = (const float*)d_in[ei + 5];
    const float* c1b    = (const float*)d_in[ei + 6];
    // gen0_Wih folded into the token table
    const float* g0Wih  = (const float*)d_in[ei + 7];
    const float* g0Whh  = (const float*)d_in[ei + 8];
    const float* g0b    = (const float*)d_in[ei + 9];
    const float* g1Wih  = (const float*)d_in[ei + 10];
    const float* g1Whh  = (const float*)d_in[ei + 11];
    const float* g1b    = (const float*)d_in[ei + 12];
    const float* outW   = (const float*)d_in[ei + 13];
    const float* outb   = (const float*)d_in[ei + 14];
    float* out = (float*)d_out;

    const int L = in_sizes[0] / B_;       // 100
    const int T = out_size / (B_ * VOC);  // 256

    setup_kernel<<<512, 256>>>(emb, c0Wih, g0Wih);
    encoder_kernel<<<NB, NTHR>>>(leftC, rightC, c0Whh, c0b, c1Wih, c1Whh, c1b, L);
    decoder_kernel<<<NB, NTHR>>>(g0Whh, g0b, g1Wih, g1Whh, g1b, outW, outb, out, T);
}